// round 16
// baseline (speedup 1.0000x reference)
#include <cuda_runtime.h>

// Problem constants (fixed shapes from reference setup_inputs)
#define NB   2
#define C    32
#define H    64
#define W    64
#define L    (H * W)      // 4096
#define CKK  288          // C * 3 * 3
#define O    32           // out channels
#define WARPS_PER_BLOCK 8
#define THREADS (WARPS_PER_BLOCK * 32)

// LDG.128 with L2 256B prefetch hint: the filter stream is perfectly
// sequential (each warp consumes contiguous 512B per iteration), so hinting
// the L2 to fetch the next 256B improves miss pipelining / HBM row locality
// at zero instruction or register cost.
__device__ __forceinline__ float4 ld4_pf(const float4* p) {
    float4 v;
    asm volatile("ld.global.L2::256B.v4.f32 {%0,%1,%2,%3}, [%4];"
                 : "=f"(v.x), "=f"(v.y), "=f"(v.z), "=f"(v.w)
                 : "l"(p));
    return v;
}

// Roofline-converged config (R13 base: fastest measured kernel, 49.95us,
// 6.14 TB/s; traffic == logical minimum 306MB). One warp per (n,l); block =
// 8 consecutive locations; single wave (1024 blocks).
// Phase 0: peel 2 filter loads. Phase 1: build unfold patch (features are
// L2-resident, 9x reuse). Phase 2: rolled unroll-7 LDG.128 stream with L2
// prefetch hint, 4 FMA chains, shfl_xor(8,16) reduction. Epilogue: stage
// results transposed in smem; 64 threads emit STG.128 full-sector stores.
__global__ __launch_bounds__(THREADS, 8)
void convfilt_kernel(const float* __restrict__ features,
                     const float* __restrict__ filters,
                     float* __restrict__ out)
{
    __shared__ float s_patch[WARPS_PER_BLOCK][CKK];
    __shared__ float s_out[O][WARPS_PER_BLOCK];   // [channel][location]

    const int warp = threadIdx.x >> 5;
    const int lane = threadIdx.x & 31;
    const int gw   = blockIdx.x * WARPS_PER_BLOCK + warp;  // 0 .. N*L-1
    const int n    = gw >> 12;        // / 4096
    const int l    = gw & (L - 1);
    const int h    = l >> 6;
    const int w    = l & (W - 1);

    const int og = lane & 7;    // output quad: channels og*4 .. og*4+3
    const int kg = lane >> 3;   // k-slice: k = kg, kg+4, kg+8, ...

    const float4* __restrict__ fp = (const float4*)
        (filters + (long long)(n * L + l) * (CKK * O) + og * 4);
    // element k, quad og lives at fp[k * (O/4)] = fp[k * 8]

    // ---- Phase 0: peel first two filter loads (independent of patch) ----
    const float4 f0 = ld4_pf(fp + (long long)(kg    ) * 8);   // t = 0
    const float4 f1 = ld4_pf(fp + (long long)(kg + 4) * 8);   // t = 1

    // ---- Phase 1: build unfold patch (k = c*9 + kh*3 + kw) ----
    #pragma unroll
    for (int k = lane; k < CKK; k += 32) {
        const int c  = k / 9;
        const int r  = k - c * 9;
        const int kh = r / 3;
        const int kw = r - kh * 3;
        const int hh = h + kh - 1;
        const int ww = w + kw - 1;
        float v = 0.0f;
        if ((unsigned)hh < (unsigned)H && (unsigned)ww < (unsigned)W)
            v = features[((n * C + c) * H + hh) * W + ww];
        s_patch[warp][k] = v;
    }
    __syncwarp();

    // ---- Phase 2: consume peeled loads, then stream the rest ----
    float4 acc = make_float4(0.f, 0.f, 0.f, 0.f);
    {
        const float s0 = s_patch[warp][kg];
        acc.x = fmaf(s0, f0.x, acc.x);
        acc.y = fmaf(s0, f0.y, acc.y);
        acc.z = fmaf(s0, f0.z, acc.z);
        acc.w = fmaf(s0, f0.w, acc.w);
        const float s1 = s_patch[warp][kg + 4];
        acc.x = fmaf(s1, f1.x, acc.x);
        acc.y = fmaf(s1, f1.y, acc.y);
        acc.z = fmaf(s1, f1.z, acc.z);
        acc.w = fmaf(s1, f1.w, acc.w);
    }

    #pragma unroll 7
    for (int t = 2; t < CKK / 4; ++t) {          // 70 iterations
        const int k = kg + 4 * t;
        const float s  = s_patch[warp][k];
        const float4 f = ld4_pf(fp + (long long)k * 8);
        acc.x = fmaf(s, f.x, acc.x);
        acc.y = fmaf(s, f.y, acc.y);
        acc.z = fmaf(s, f.z, acc.z);
        acc.w = fmaf(s, f.w, acc.w);
    }

    // ---- Reduce across the 4 k-slices (lanes differing in bits 3,4) ----
    #pragma unroll
    for (int m = 8; m <= 16; m <<= 1) {
        acc.x += __shfl_xor_sync(0xffffffffu, acc.x, m);
        acc.y += __shfl_xor_sync(0xffffffffu, acc.y, m);
        acc.z += __shfl_xor_sync(0xffffffffu, acc.z, m);
        acc.w += __shfl_xor_sync(0xffffffffu, acc.w, m);
    }

    // ---- Stage results transposed: s_out[channel][location] ----
    if (kg == 0) {
        const int obase = og * 4;
        s_out[obase + 0][warp] = fmaxf(acc.x, 0.0f);
        s_out[obase + 1][warp] = fmaxf(acc.y, 0.0f);
        s_out[obase + 2][warp] = fmaxf(acc.z, 0.0f);
        s_out[obase + 3][warp] = fmaxf(acc.w, 0.0f);
    }
    __syncthreads();

    // ---- Epilogue: 64 threads write 8 locations x 32 channels as STG.128.
    // thread t -> channel o = t>>1, location quad lo4 = (t&1)*4.
    // blockIdx*8 is 8-aligned within L -> 16B-aligned addresses.
    if (threadIdx.x < 64) {
        const int o   = threadIdx.x >> 1;
        const int lo4 = (threadIdx.x & 1) * 4;
        const int lbase = (blockIdx.x * WARPS_PER_BLOCK) & (L - 1);
        const float4 v = *(const float4*)&s_out[o][lo4];
        __stcs((float4*)&out[(n * O + o) * L + lbase + lo4], v);
    }
}

extern "C" void kernel_launch(void* const* d_in, const int* in_sizes, int n_in,
                              void* d_out, int out_size)
{
    const float* features = (const float*)d_in[0];  // [2,32,64,64]
    const float* filters  = (const float*)d_in[1];  // [2,4096,288,32]
    float* out = (float*)d_out;                     // [2,32,64,64]

    const int total_warps = NB * L;                 // 8192
    const int grid = total_warps / WARPS_PER_BLOCK; // 1024
    convfilt_kernel<<<grid, THREADS>>>(features, filters, out);
}